// round 16
// baseline (speedup 1.0000x reference)
#include <cuda_runtime.h>
#include <cuda_fp16.h>
#include <math.h>
#include <stdint.h>

#define BB 2
#define NNq 2048
#define CCd 1024
#define HHn 16
#define HIDd 4096
#define ROWS (BB * NNq)   // 4096

// ================= scratch (device globals) =================
__device__ __half g_x1h[ROWS * CCd];
__device__ __half g_h1h[ROWS * HIDd];
__device__ __half g_ah[ROWS * CCd];
__device__ __half g_att[ROWS * CCd];
__device__ __half g_q2[ROWS * CCd];
__device__ __half g_k2[ROWS * CCd];
__device__ __half g_v2[ROWS * CCd];
__device__ __half g_wq[3072 * 1024];
__device__ __half g_wp[1024 * 1024];
__device__ __half g_w1[4096 * 1024];           // ln2_g-folded
__device__ __half g_w2[1024 * 4096];           // ffln_g-folded
__device__ float g_ps1[ROWS * 8], g_pq1[ROWS * 8];
__device__ float g_ps2[ROWS * 32], g_pq2[ROWS * 32];
__device__ float g_u1[HIDd], g_t1[HIDd];
__device__ float g_u2[CCd], g_t2[CCd];
__device__ float g_pu[32 * HIDd], g_pt[32 * HIDd];

// ================= helpers =================
__device__ __forceinline__ uint32_t smem_u32(const void* p) {
  uint32_t a;
  asm("{ .reg .u64 t; cvta.to.shared.u64 t, %1; cvt.u32.u64 %0, t; }"
      : "=r"(a) : "l"(p));
  return a;
}

#define CP_ASYNC16(sm, gp) \
  asm volatile("cp.async.cg.shared.global [%0], [%1], 16;" \
               :: "r"(sm), "l"(gp) : "memory")
#define CP_COMMIT() asm volatile("cp.async.commit_group;" ::: "memory")
#define CP_WAIT0() asm volatile("cp.async.wait_group 0;" ::: "memory")
#define CP_WAIT1() asm volatile("cp.async.wait_group 1;" ::: "memory")

#define LDSM_X4(r0, r1, r2, r3, a) \
  asm volatile("ldmatrix.sync.aligned.m8n8.x4.shared.b16 {%0,%1,%2,%3}, [%4];" \
               : "=r"(r0), "=r"(r1), "=r"(r2), "=r"(r3) : "r"(a))
#define LDSM_X4_T(r0, r1, r2, r3, a) \
  asm volatile("ldmatrix.sync.aligned.m8n8.x4.trans.shared.b16 {%0,%1,%2,%3}, [%4];" \
               : "=r"(r0), "=r"(r1), "=r"(r2), "=r"(r3) : "r"(a))

#define MMA16816(d, a0, a1, a2, a3, b0, b1) \
  asm volatile("mma.sync.aligned.m16n8k16.row.col.f32.f16.f16.f32 " \
               "{%0,%1,%2,%3}, {%4,%5,%6,%7}, {%8,%9}, {%0,%1,%2,%3};" \
               : "+f"((d)[0]), "+f"((d)[1]), "+f"((d)[2]), "+f"((d)[3]) \
               : "r"(a0), "r"(a1), "r"(a2), "r"(a3), "r"(b0), "r"(b1))

__device__ __forceinline__ float gelu_f(float v) {
  return 0.5f * v * (1.f + erff(v * 0.70710678118654752f));
}

// ========== weight convert + transpose (+optional row-scale fold) ==========
__global__ __launch_bounds__(256) void wconv_kernel(
    const float* __restrict__ W, const float* __restrict__ scale,
    __half* __restrict__ th, int K, int N) {
  __shared__ float t[64][33];
  int n0 = blockIdx.x * 32, k0 = blockIdx.y * 64;
  int tn = threadIdx.x & 31, tk = threadIdx.x >> 5;
#pragma unroll
  for (int i = 0; i < 8; i++)
    t[tk + i * 8][tn] = W[(size_t)(k0 + tk + i * 8) * N + n0 + tn];
  __syncthreads();
  int wn = threadIdx.x >> 3, wk = (threadIdx.x & 7) * 8;
  __half tmp[8];
#pragma unroll
  for (int i = 0; i < 8; i++) {
    float v = t[wk + i][wn];
    if (scale) v *= scale[k0 + wk + i];
    tmp[i] = __float2half_rn(v);
  }
  *(uint4*)(th + (size_t)(n0 + wn) * K + k0 + wk) = *(uint4*)tmp;
}

// ========== u/t partials: chunked column sums (deterministic) ==========
__global__ __launch_bounds__(256) void ut_part_kernel(
    const float* __restrict__ W, const float* __restrict__ g,
    const float* __restrict__ b, int N,
    float* __restrict__ pu, float* __restrict__ pt) {
  int n = blockIdx.x * 256 + threadIdx.x;
  int k0 = blockIdx.y * 128;
  float su = 0.f, st = 0.f;
  for (int c = 0; c < 128; c++) {
    float w = W[(size_t)(k0 + c) * N + n];
    su += g[k0 + c] * w;
    st += b[k0 + c] * w;
  }
  pu[(size_t)blockIdx.y * N + n] = su;
  pt[(size_t)blockIdx.y * N + n] = st;
}

__global__ __launch_bounds__(256) void ut_red_kernel(
    const float* __restrict__ pu, const float* __restrict__ pt, int nch,
    int N, float* __restrict__ u, float* __restrict__ t) {
  int n = blockIdx.x * 256 + threadIdx.x;
  float su = 0.f, st = 0.f;
  for (int i = 0; i < nch; i++) {
    su += pu[(size_t)i * N + n];
    st += pt[(size_t)i * N + n];
  }
  u[n] = su;
  t[n] = st;
}

// ================= LayerNorm (fp32 in, 1024) -> fp16 =================
__global__ __launch_bounds__(256) void ln_h_kernel(
    const float* __restrict__ in, const float* __restrict__ gw,
    const float* __restrict__ bw, __half* __restrict__ oh) {
  const int cols = 1024;
  int row = blockIdx.x;
  const float* rp = in + (size_t)row * cols;
  int c = threadIdx.x * 4;
  float4 v = *(const float4*)(rp + c);
  float s = v.x + v.y + v.z + v.w;
  float sq = v.x * v.x + v.y * v.y + v.z * v.z + v.w * v.w;
  __shared__ float red0[8], red1[8];
#pragma unroll
  for (int o = 16; o; o >>= 1) {
    s += __shfl_xor_sync(0xffffffff, s, o);
    sq += __shfl_xor_sync(0xffffffff, sq, o);
  }
  int warp = threadIdx.x >> 5, lane = threadIdx.x & 31;
  if (lane == 0) { red0[warp] = s; red1[warp] = sq; }
  __syncthreads();
  __shared__ float s_mu, s_ri;
  if (threadIdx.x == 0) {
    float ts = 0.f, tq = 0.f;
#pragma unroll
    for (int i = 0; i < 8; i++) { ts += red0[i]; tq += red1[i]; }
    float mu = ts / (float)cols;
    float var = tq / (float)cols - mu * mu;
    s_mu = mu;
    s_ri = rsqrtf(var + 1e-5f);
  }
  __syncthreads();
  float mu = s_mu, ri = s_ri;
  float4 g4 = *(const float4*)(gw + c);
  float4 b4 = *(const float4*)(bw + c);
  __half2 h01, h23;
  h01.x = __float2half_rn((v.x - mu) * ri * g4.x + b4.x);
  h01.y = __float2half_rn((v.y - mu) * ri * g4.y + b4.y);
  h23.x = __float2half_rn((v.z - mu) * ri * g4.z + b4.z);
  h23.y = __float2half_rn((v.w - mu) * ri * g4.w + b4.w);
  size_t o = (size_t)row * cols + c;
  *(__half2*)(oh + o) = h01;
  *(__half2*)(oh + o + 2) = h23;
}

// ================= mma.sync fp16 GEMM (BK=64, 3-stage) =================
// EPI 3: QKV (bias + qscale + RoPE + split fp16)
// EPI 4: bias + res(fp32) -> fp16(hout), + row-stats partials
// EPI 6: in-prologue stats reduce + LN fold + bias + GELU -> fp16 + partials
// EPI 7: in-prologue stats reduce + LN fold + bias + resh(fp16) -> fp32(C)
#define GPITCH 144
#define TILE_H (128 * GPITCH)
#define STAGE_H (2 * TILE_H)
#define GEMM_SMEM (3 * STAGE_H)
#define GEMM_SMEM_X (GEMM_SMEM + 1024)   // + mu/ri buffer
#define QSCALE 0.1803368801111244f

template <int EPI>
__global__ __launch_bounds__(256, 2) void gemm_mma(
    const __half* __restrict__ Ah, const __half* __restrict__ Bh,
    const float* __restrict__ bias, const float* __restrict__ res,
    const __half* __restrict__ resh,
    float* __restrict__ C, int K, int N,
    __half* hout, __half* k_, __half* v_,
    const float* __restrict__ pin_s, const float* __restrict__ pin_q,
    int nbin, float invNin,
    const float* __restrict__ uv, const float* __restrict__ tv,
    float* __restrict__ psum, float* __restrict__ psq, int nbp) {
  extern __shared__ char smem[];
  uint32_t sb = smem_u32(smem);
  int tid = threadIdx.x, wid = tid >> 5, lane = tid & 31;
  int m0 = blockIdx.y * 128, n0 = blockIdx.x * 128;
  int wm = wid & 1, wn = wid >> 1;
  int lrow = lane & 15, lc8 = (lane >> 4) * 8;
  float* smu = (float*)(smem + GEMM_SMEM);
  float* sri = smu + 128;

  float acc[4][4][4];
#pragma unroll
  for (int i = 0; i < 4; i++)
#pragma unroll
    for (int j = 0; j < 4; j++)
#pragma unroll
      for (int t = 0; t < 4; t++) acc[i][j][t] = 0.f;

  int NCH = K >> 6;

#define GEMM_LOADS(stgbase, ktv)                                             \
  {                                                                          \
    uint32_t stg = (stgbase);                                                \
    int kt = (ktv);                                                          \
    _Pragma("unroll") for (int i = 0; i < 4; i++) {                          \
      int c = tid + i * 256;                                                 \
      int r = c >> 3, q = c & 7;                                             \
      uint32_t so = (uint32_t)(r * GPITCH + q * 16);                         \
      CP_ASYNC16(stg + so, Ah + (size_t)(m0 + r) * K + kt + q * 8);          \
      CP_ASYNC16(stg + TILE_H + so, Bh + (size_t)(n0 + r) * K + kt + q * 8); \
    }                                                                        \
    CP_COMMIT();                                                             \
  }

  GEMM_LOADS(sb, 0);
  GEMM_LOADS(sb + STAGE_H, 64);

  // in-prologue stats reduce (overlaps with cp.async fills); consumed in
  // the epilogue only; intervening __syncthreads in the main loop orders it.
  if ((EPI == 6 || EPI == 7) && tid < 128) {
    float s = 0.f, q = 0.f;
    for (int i = 0; i < nbin; i++) {
      s += pin_s[(size_t)(m0 + tid) * nbin + i];
      q += pin_q[(size_t)(m0 + tid) * nbin + i];
    }
    float m = s * invNin;
    float var = q * invNin - m * m;
    smu[tid] = m;
    sri[tid] = rsqrtf(var + 1e-5f);
  }

  for (int kc = 0; kc < NCH; kc++) {
    if (kc + 1 < NCH) { CP_WAIT1(); } else { CP_WAIT0(); }
    __syncthreads();
    if (kc + 2 < NCH) GEMM_LOADS(sb + ((kc + 2) % 3) * STAGE_H, (kc + 2) * 64);

    uint32_t stA = sb + (kc % 3) * STAGE_H;
    uint32_t stB = stA + TILE_H;

#pragma unroll
    for (int ks = 0; ks < 64; ks += 16) {
      uint32_t bhf[8];
      uint32_t boff0 = (uint32_t)((wn * 32 + lrow) * GPITCH + (ks + lc8) * 2);
      uint32_t boff1 = (uint32_t)((wn * 32 + 16 + lrow) * GPITCH + (ks + lc8) * 2);
      LDSM_X4(bhf[0], bhf[1], bhf[2], bhf[3], stB + boff0);
      LDSM_X4(bhf[4], bhf[5], bhf[6], bhf[7], stB + boff1);
#pragma unroll
      for (int mb = 0; mb < 4; mb++) {
        uint32_t ah[4];
        uint32_t aoff = (uint32_t)((wm * 64 + mb * 16 + lrow) * GPITCH + (ks + lc8) * 2);
        LDSM_X4(ah[0], ah[1], ah[2], ah[3], stA + aoff);
#pragma unroll
        for (int nb = 0; nb < 4; nb++) {
          int pi = (nb >> 1) * 4, od = nb & 1;
          MMA16816(acc[mb][nb], ah[0], ah[1], ah[2], ah[3],
                   bhf[pi + od], bhf[pi + 2 + od]);
        }
      }
    }
  }

  int erow = lane >> 2, ecol = (lane & 3) * 2;
  float rs[4][2], rq[4][2];
  if (EPI == 4 || EPI == 6) {
#pragma unroll
    for (int i = 0; i < 4; i++) {
      rs[i][0] = rs[i][1] = 0.f;
      rq[i][0] = rq[i][1] = 0.f;
    }
  }

#pragma unroll
  for (int mb = 0; mb < 4; mb++) {
    int gr = m0 + wm * 64 + mb * 16 + erow;
    int lr0 = wm * 64 + mb * 16 + erow;
    float mur0, rir0, mur1, rir1;
    if (EPI == 6 || EPI == 7) {
      mur0 = smu[lr0]; rir0 = sri[lr0];
      mur1 = smu[lr0 + 8]; rir1 = sri[lr0 + 8];
    }
#pragma unroll
    for (int nb = 0; nb < 4; nb++) {
      float* d = acc[mb][nb];
      int gc = n0 + wn * 32 + nb * 8 + ecol;
      float2 b2 = *(const float2*)(bias + gc);
      float v0, v1, v2, v3;
      if (EPI == 6 || EPI == 7) {
        float2 u2 = *(const float2*)(uv + gc);
        float2 t2 = *(const float2*)(tv + gc);
        v0 = rir0 * (d[0] - mur0 * u2.x) + t2.x + b2.x;
        v1 = rir0 * (d[1] - mur0 * u2.y) + t2.y + b2.y;
        v2 = rir1 * (d[2] - mur1 * u2.x) + t2.x + b2.x;
        v3 = rir1 * (d[3] - mur1 * u2.y) + t2.y + b2.y;
      } else {
        v0 = d[0] + b2.x; v1 = d[1] + b2.y;
        v2 = d[2] + b2.x; v3 = d[3] + b2.y;
      }
      if (EPI == 3) {
        int region = gc >> 10;
        int hh = (gc & 1023) >> 6;
        int dd = gc & 63;
        int b = gr >> 11;
        int n = gr & 2047;
        if (region < 2) {
          float inv = 1.0f / powf(10000.0f, (float)(dd & ~1) / 64.0f);
          float c0, s0, c1, s1;
          sincosf((float)n * inv, &s0, &c0);
          sincosf((float)(n + 8) * inv, &s1, &c1);
          float r0 = v0 * c0 - v1 * s0, r1 = v1 * c0 + v0 * s0;
          float r2 = v2 * c1 - v3 * s1, r3 = v3 * c1 + v2 * s1;
          v0 = r0; v1 = r1; v2 = r2; v3 = r3;
          if (region == 0) { v0 *= QSCALE; v1 *= QSCALE; v2 *= QSCALE; v3 *= QSCALE; }
        }
        __half* dst = (region == 0) ? hout : (region == 1) ? k_ : v_;
        size_t o0 = ((size_t)((b * 16 + hh) * 2048 + n)) * 64 + dd;
        size_t o1 = o0 + 8 * 64;
        *(__half2*)(dst + o0) = __floats2half2_rn(v0, v1);
        *(__half2*)(dst + o1) = __floats2half2_rn(v2, v3);
      } else if (EPI == 4) {
        float2 r0 = *(const float2*)(res + (size_t)gr * N + gc);
        float2 r1 = *(const float2*)(res + (size_t)(gr + 8) * N + gc);
        v0 += r0.x; v1 += r0.y; v2 += r1.x; v3 += r1.y;
        rs[mb][0] += v0 + v1; rq[mb][0] += v0 * v0 + v1 * v1;
        rs[mb][1] += v2 + v3; rq[mb][1] += v2 * v2 + v3 * v3;
        *(__half2*)(hout + (size_t)gr * N + gc) = __floats2half2_rn(v0, v1);
        *(__half2*)(hout + (size_t)(gr + 8) * N + gc) = __floats2half2_rn(v2, v3);
      } else if (EPI == 6) {
        v0 = gelu_f(v0); v1 = gelu_f(v1);
        v2 = gelu_f(v2); v3 = gelu_f(v3);
        rs[mb][0] += v0 + v1; rq[mb][0] += v0 * v0 + v1 * v1;
        rs[mb][1] += v2 + v3; rq[mb][1] += v2 * v2 + v3 * v3;
        *(__half2*)(hout + (size_t)gr * N + gc) = __floats2half2_rn(v0, v1);
        *(__half2*)(hout + (size_t)(gr + 8) * N + gc) = __floats2half2_rn(v2, v3);
      } else if (EPI == 7) {
        __half2 r0 = *(const __half2*)(resh + (size_t)gr * N + gc);
        __half2 r1 = *(const __half2*)(resh + (size_t)(gr + 8) * N + gc);
        float2 f0 = __half22float2(r0), f1 = __half22float2(r1);
        v0 += f0.x; v1 += f0.y; v2 += f1.x; v3 += f1.y;
        float2 o0 = {v0, v1}, o1 = {v2, v3};
        *(float2*)(C + (size_t)gr * N + gc) = o0;
        *(float2*)(C + (size_t)(gr + 8) * N + gc) = o1;
      }
    }
  }

  if (EPI == 4 || EPI == 6) {
    __syncthreads();
    float2* part = (float2*)smem;
#pragma unroll
    for (int mb = 0; mb < 4; mb++) {
#pragma unroll
      for (int h = 0; h < 2; h++) {
        float s = rs[mb][h], q = rq[mb][h];
        s += __shfl_xor_sync(0xffffffff, s, 1);
        s += __shfl_xor_sync(0xffffffff, s, 2);
        q += __shfl_xor_sync(0xffffffff, q, 1);
        q += __shfl_xor_sync(0xffffffff, q, 2);
        if ((lane & 3) == 0) {
          int r = wm * 64 + mb * 16 + erow + h * 8;
          float2 sq2 = {s, q};
          part[r * 4 + wn] = sq2;
        }
      }
    }
    __syncthreads();
    if (tid < 128) {
      float2 a = part[tid * 4 + 0], b = part[tid * 4 + 1];
      float2 c = part[tid * 4 + 2], dd = part[tid * 4 + 3];
      psum[(size_t)(m0 + tid) * nbp + blockIdx.x] = a.x + b.x + c.x + dd.x;
      psq[(size_t)(m0 + tid) * nbp + blockIdx.x] = a.y + b.y + c.y + dd.y;
    }
  }
}

// ================= FA2 flash attention =================
#define APB 144
#define A_oQ 0
#define A_oKV 18432
#define ATTN_SMEM (18432 + 3 * 18432)

__global__ __launch_bounds__(256, 2) void attn_mma(
    const __half* __restrict__ qg, const __half* __restrict__ kg_,
    const __half* __restrict__ vg, __half* __restrict__ og) {
  extern __shared__ char sm[];
  uint32_t sb = smem_u32(sm);

  int tid = threadIdx.x, wid = tid >> 5, lane = tid & 31;
  int lrow = lane & 15, lc8 = (lane >> 4) * 8;
  int erow = lane >> 2, ecol = (lane & 3) * 2;
  int bh = blockIdx.y, qt = blockIdx.x;
  size_t base = (size_t)bh * (2048 * 64);

  {
    const __half* gq = qg + base + (size_t)(qt * 128) * 64;
#pragma unroll
    for (int i = 0; i < 4; i++) {
      int f = tid + i * 256;
      int r = f >> 3, c8 = f & 7;
      CP_ASYNC16(sb + A_oQ + (uint32_t)(r * APB + c8 * 16), gq + r * 64 + c8 * 8);
    }
    CP_COMMIT();
  }

#define ATTN_KV_LOADS(stg, ktv)                                              \
  {                                                                          \
    int kt_ = (ktv);                                                         \
    uint32_t d0 = sb + A_oKV + (stg) * 18432;                                \
    _Pragma("unroll") for (int i = 0; i < 2; i++) {                          \
      int f = tid + i * 256;                                                 \
      int r = f >> 3, c8 = f & 7;                                            \
      uint32_t so = (uint32_t)(r * APB + c8 * 16);                           \
      size_t go = base + (size_t)(kt_ * 64 + r) * 64 + c8 * 8;               \
      CP_ASYNC16(d0 + so, kg_ + go);                                         \
      CP_ASYNC16(d0 + 9216 + so, vg + go);                                   \
    }                                                                        \
    CP_COMMIT();                                                             \
  }

  ATTN_KV_LOADS(0, 0);
  ATTN_KV_LOADS(1, 1);

  float oacc[8][4];
#pragma unroll
  for (int j = 0; j < 8; j++)
#pragma unroll
    for (int t = 0; t < 4; t++) oacc[j][t] = 0.f;
  float m_lo = -INFINITY, m_hi = -INFINITY, l_lo = 0.f, l_hi = 0.f;

  uint32_t qbase = sb + A_oQ + (uint32_t)((wid * 16 + lrow) * APB + lc8 * 2);
  uint32_t aq[4][4];

  for (int kt = 0; kt < 32; kt++) {
    if (kt + 1 < 32) { CP_WAIT1(); } else { CP_WAIT0(); }
    __syncthreads();
    if (kt + 2 < 32) ATTN_KV_LOADS((kt + 2) % 3, kt + 2);
    if (kt == 0) {
#pragma unroll
      for (int ks = 0; ks < 4; ks++)
        LDSM_X4(aq[ks][0], aq[ks][1], aq[ks][2], aq[ks][3], qbase + ks * 32);
    }

    uint32_t sK = sb + A_oKV + (kt % 3) * 18432;
    uint32_t sV = sK + 9216;

    float sacc[8][4];
#pragma unroll
    for (int j = 0; j < 8; j++)
#pragma unroll
      for (int t = 0; t < 4; t++) sacc[j][t] = 0.f;
#pragma unroll
    for (int ks = 0; ks < 4; ks++) {
#pragma unroll
      for (int g = 0; g < 4; g++) {
        uint32_t kb[4];
        uint32_t koff = (uint32_t)((g * 16 + lrow) * APB + (ks * 16 + lc8) * 2);
        LDSM_X4(kb[0], kb[1], kb[2], kb[3], sK + koff);
        MMA16816(sacc[g * 2 + 0], aq[ks][0], aq[ks][1], aq[ks][2], aq[ks][3],
                 kb[0], kb[2]);
        MMA16816(sacc[g * 2 + 1], aq[ks][0], aq[ks][1], aq[ks][2], aq[ks][3],
                 kb[1], kb[3]);
      }
    }

    float mx0 = -INFINITY, mx1 = -INFINITY;
#pragma unroll
    for (int j = 0; j < 8; j++) {
      mx0 = fmaxf(mx0, fmaxf(sacc[j][0], sacc[j][1]));
      mx1 = fmaxf(mx1, fmaxf(sacc[j][2], sacc[j][3]));
    }
    mx0 = fmaxf(mx0, __shfl_xor_sync(0xffffffff, mx0, 1));
    mx0 = fmaxf(mx0, __shfl_xor_sync(0xffffffff, mx0, 2));
    mx1 = fmaxf(mx1, __shfl_xor_sync(0xffffffff, mx1, 1));
    mx1 = fmaxf(mx1, __shfl_xor_sync(0xffffffff, mx1, 2));
    float nm0 = fmaxf(m_lo, mx0), nm1 = fmaxf(m_hi, mx1);
    float cf0 = exp2f(m_lo - nm0), cf1 = exp2f(m_hi - nm1);
    m_lo = nm0; m_hi = nm1;

    uint32_t pa[4][4];
    float s0 = 0.f, s1 = 0.f;
#pragma unroll
    for (int g = 0; g < 4; g++) {
#pragma unroll
      for (int hb = 0; hb < 2; hb++) {
        int j = g * 2 + hb;
        float p00 = exp2f(sacc[j][0] - nm0);
        float p01 = exp2f(sacc[j][1] - nm0);
        float p10 = exp2f(sacc[j][2] - nm1);
        float p11 = exp2f(sacc[j][3] - nm1);
        s0 += p00 + p01;
        s1 += p10 + p11;
        __half2 plo = __floats2half2_rn(p00, p01);
        __half2 phi = __floats2half2_rn(p10, p11);
        pa[g][hb * 2 + 0] = *(uint32_t*)&plo;
        pa[g][hb * 2 + 1] = *(uint32_t*)&phi;
      }
    }
    s0 += __shfl_xor_sync(0xffffffff, s0, 1);
    s0 += __shfl_xor_sync(0xffffffff, s0, 2);
    s1 += __shfl_xor_sync(0xffffffff, s1, 1);
    s1 += __shfl_xor_sync(0xffffffff, s1, 2);
    l_lo = l_lo * cf0 + s0;
    l_hi = l_hi * cf1 + s1;

#pragma unroll
    for (int j = 0; j < 8; j++) {
      oacc[j][0] *= cf0; oacc[j][1] *= cf0;
      oacc[j][2] *= cf1; oacc[j][3] *= cf1;
    }
#pragma unroll
    for (int g = 0; g < 4; g++) {
#pragma unroll
      for (int db = 0; db < 4; db++) {
        uint32_t vb[4];
        uint32_t voff = (uint32_t)((g * 16 + lrow) * APB + (db * 16 + lc8) * 2);
        LDSM_X4_T(vb[0], vb[1], vb[2], vb[3], sV + voff);
        MMA16816(oacc[db * 2 + 0], pa[g][0], pa[g][1], pa[g][2], pa[g][3],
                 vb[0], vb[1]);
        MMA16816(oacc[db * 2 + 1], pa[g][0], pa[g][1], pa[g][2], pa[g][3],
                 vb[2], vb[3]);
      }
    }
  }

  int b = bh >> 4, h = bh & 15;
  float il0 = 1.f / l_lo, il1 = 1.f / l_hi;
  int qrow = qt * 128 + wid * 16 + erow;
  size_t rbase0 = ((size_t)(b * 2048 + qrow)) * 1024 + h * 64;
  size_t rbase1 = rbase0 + 8 * 1024;
#pragma unroll
  for (int db = 0; db < 4; db++) {
#pragma unroll
    for (int nb = 0; nb < 2; nb++) {
      int j = db * 2 + nb;
      int d = db * 16 + nb * 8 + ecol;
      *(__half2*)(og + rbase0 + d) = __floats2half2_rn(oacc[j][0] * il0,
                                                       oacc[j][1] * il0);
      *(__half2*)(og + rbase1 + d) = __floats2half2_rn(oacc[j][2] * il1,
                                                       oacc[j][3] * il1);
    }
  }
}

// ================= launch =================
extern "C" void kernel_launch(void* const* d_in, const int* in_sizes, int n_in,
                              void* d_out, int out_size) {
  const float* x = (const float*)d_in[0];
  const float* ln1_g = (const float*)d_in[1];
  const float* ln1_b = (const float*)d_in[2];
  const float* qkv_w = (const float*)d_in[3];
  const float* qkv_b = (const float*)d_in[4];
  const float* proj_w = (const float*)d_in[5];
  const float* proj_b = (const float*)d_in[6];
  const float* ln2_g = (const float*)d_in[7];
  const float* ln2_b = (const float*)d_in[8];
  const float* fc1_w = (const float*)d_in[9];
  const float* fc1_b = (const float*)d_in[10];
  const float* ffln_g = (const float*)d_in[11];
  const float* ffln_b = (const float*)d_in[12];
  const float* fc2_w = (const float*)d_in[13];
  const float* fc2_b = (const float*)d_in[14];
  float* out = (float*)d_out;

  __half *x1h, *h1h, *ah, *att, *q, *k, *v;
  __half *wq, *wp, *w1, *w2;
  float *ps1, *pq1, *ps2, *pq2, *u1, *t1, *u2, *t2, *pu, *pt;
  cudaGetSymbolAddress((void**)&x1h, g_x1h);
  cudaGetSymbolAddress((void**)&h1h, g_h1h);
  cudaGetSymbolAddress((void**)&ah, g_ah);
  cudaGetSymbolAddress((void**)&att, g_att);
  cudaGetSymbolAddress((void**)&q, g_q2);
  cudaGetSymbolAddress((void**)&k, g_k2);
  cudaGetSymbolAddress((void**)&v, g_v2);
  cudaGetSymbolAddress((void**)&wq, g_wq);
  cudaGetSymbolAddress((void**)&wp, g_wp);
  cudaGetSymbolAddress((void**)&w1, g_w1);
  cudaGetSymbolAddress((void**)&w2, g_w2);
  cudaGetSymbolAddress((void**)&ps1, g_ps1);
  cudaGetSymbolAddress((void**)&pq1, g_pq1);
  cudaGetSymbolAddress((void**)&ps2, g_ps2);
  cudaGetSymbolAddress((void**)&pq2, g_pq2);
  cudaGetSymbolAddress((void**)&u1, g_u1);
  cudaGetSymbolAddress((void**)&t1, g_t1);
  cudaGetSymbolAddress((void**)&u2, g_u2);
  cudaGetSymbolAddress((void**)&t2, g_t2);
  cudaGetSymbolAddress((void**)&pu, g_pu);
  cudaGetSymbolAddress((void**)&pt, g_pt);

  cudaFuncSetAttribute(gemm_mma<3>, cudaFuncAttributeMaxDynamicSharedMemorySize, GEMM_SMEM_X);
  cudaFuncSetAttribute(gemm_mma<4>, cudaFuncAttributeMaxDynamicSharedMemorySize, GEMM_SMEM_X);
  cudaFuncSetAttribute(gemm_mma<6>, cudaFuncAttributeMaxDynamicSharedMemorySize, GEMM_SMEM_X);
  cudaFuncSetAttribute(gemm_mma<7>, cudaFuncAttributeMaxDynamicSharedMemorySize, GEMM_SMEM_X);
  cudaFuncSetAttribute(attn_mma, cudaFuncAttributeMaxDynamicSharedMemorySize, ATTN_SMEM);

  // --- side stream: weight conversion + u/t vectors ---
  cudaStream_t s1;
  cudaStreamCreateWithFlags(&s1, cudaStreamNonBlocking);
  cudaEvent_t evRoot, evQ, evP, evW;
  cudaEventCreateWithFlags(&evRoot, cudaEventDisableTiming);
  cudaEventCreateWithFlags(&evQ, cudaEventDisableTiming);
  cudaEventCreateWithFlags(&evP, cudaEventDisableTiming);
  cudaEventCreateWithFlags(&evW, cudaEventDisableTiming);

  cudaEventRecord(evRoot, 0);
  cudaStreamWaitEvent(s1, evRoot, 0);

  wconv_kernel<<<dim3(3072 / 32, 1024 / 64), 256, 0, s1>>>(qkv_w, nullptr, wq, 1024, 3072);
  cudaEventRecord(evQ, s1);
  wconv_kernel<<<dim3(1024 / 32, 1024 / 64), 256, 0, s1>>>(proj_w, nullptr, wp, 1024, 1024);
  cudaEventRecord(evP, s1);
  wconv_kernel<<<dim3(4096 / 32, 1024 / 64), 256, 0, s1>>>(fc1_w, ln2_g, w1, 1024, 4096);
  wconv_kernel<<<dim3(1024 / 32, 4096 / 64), 256, 0, s1>>>(fc2_w, ffln_g, w2, 4096, 1024);
  ut_part_kernel<<<dim3(4096 / 256, 1024 / 128), 256, 0, s1>>>(fc1_w, ln2_g, ln2_b, 4096, pu, pt);
  ut_red_kernel<<<4096 / 256, 256, 0, s1>>>(pu, pt, 8, 4096, u1, t1);
  ut_part_kernel<<<dim3(1024 / 256, 4096 / 128), 256, 0, s1>>>(fc2_w, ffln_g, ffln_b, 1024, pu, pt);
  ut_red_kernel<<<1024 / 256, 256, 0, s1>>>(pu, pt, 32, 1024, u2, t2);
  cudaEventRecord(evW, s1);

  // main branch
  // 1) LN1 -> fp16
  ln_h_kernel<<<ROWS, 256>>>(x, ln1_g, ln1_b, ah);
  // 2) QKV GEMM (needs wq)
  cudaStreamWaitEvent(0, evQ, 0);
  gemm_mma<3><<<dim3(3072 / 128, ROWS / 128), 256, GEMM_SMEM_X>>>(
      ah, wq, qkv_b, nullptr, nullptr, nullptr, 1024, 3072, q, k, v,
      nullptr, nullptr, 0, 0.f, nullptr, nullptr, nullptr, nullptr, 0);
  // 3) attention
  attn_mma<<<dim3(NNq / 128, BB * HHn), 256, ATTN_SMEM>>>(q, k, v, att);
  // 4) proj + residual(x) -> x1h + stats partials (needs wp only)
  cudaStreamWaitEvent(0, evP, 0);
  gemm_mma<4><<<dim3(1024 / 128, ROWS / 128), 256, GEMM_SMEM_X>>>(
      att, wp, proj_b, x, nullptr, nullptr, 1024, 1024, x1h, nullptr, nullptr,
      nullptr, nullptr, 0, 0.f, nullptr, nullptr, ps1, pq1, 8);
  // 5) fc1 (LN2 folded, in-prologue stats) + GELU -> h1h + partials
  cudaStreamWaitEvent(0, evW, 0);
  gemm_mma<6><<<dim3(4096 / 128, ROWS / 128), 256, GEMM_SMEM_X>>>(
      x1h, w1, fc1_b, nullptr, nullptr, nullptr, 1024, 4096, h1h, nullptr, nullptr,
      ps1, pq1, 8, 1.0f / 1024.0f, u1, t1, ps2, pq2, 32);
  // 6) fc2 (ffn-LN folded, in-prologue stats) + residual(x1h) -> out fp32
  gemm_mma<7><<<dim3(1024 / 128, ROWS / 128), 256, GEMM_SMEM_X>>>(
      h1h, w2, fc2_b, nullptr, x1h, out, 4096, 1024, nullptr, nullptr, nullptr,
      ps2, pq2, 32, 1.0f / 4096.0f, u2, t2, nullptr, nullptr, 0);
}

// round 17
// speedup vs baseline: 1.0031x; 1.0031x over previous
#include <cuda_runtime.h>
#include <cuda_fp16.h>
#include <math.h>
#include <stdint.h>

#define BB 2
#define NNq 2048
#define CCd 1024
#define HHn 16
#define HIDd 4096
#define ROWS (BB * NNq)   // 4096

// ================= scratch (device globals) =================
__device__ __half g_x1h[ROWS * CCd];
__device__ __half g_h1h[ROWS * HIDd];
__device__ __half g_ah[ROWS * CCd];
__device__ __half g_att[ROWS * CCd];
__device__ __half g_q2[ROWS * CCd];
__device__ __half g_k2[ROWS * CCd];
__device__ __half g_v2[ROWS * CCd];
__device__ __half g_wq[3072 * 1024];
__device__ __half g_wp[1024 * 1024];
__device__ __half g_w1[4096 * 1024];           // ln2_g-folded
__device__ __half g_w2[1024 * 4096];           // ffln_g-folded
__device__ float g_ps1[ROWS * 8], g_pq1[ROWS * 8];
__device__ float g_ps2[ROWS * 32], g_pq2[ROWS * 32];
__device__ float g_u1[HIDd], g_t1[HIDd];
__device__ float g_u2[CCd], g_t2[CCd];
__device__ float g_pu[32 * HIDd], g_pt[32 * HIDd];
__device__ float2 g_rope[NNq * 32];            // cos/sin LUT [n][i]

// ================= helpers =================
__device__ __forceinline__ uint32_t smem_u32(const void* p) {
  uint32_t a;
  asm("{ .reg .u64 t; cvta.to.shared.u64 t, %1; cvt.u32.u64 %0, t; }"
      : "=r"(a) : "l"(p));
  return a;
}

#define CP_ASYNC16(sm, gp) \
  asm volatile("cp.async.cg.shared.global [%0], [%1], 16;" \
               :: "r"(sm), "l"(gp) : "memory")
#define CP_COMMIT() asm volatile("cp.async.commit_group;" ::: "memory")
#define CP_WAIT0() asm volatile("cp.async.wait_group 0;" ::: "memory")
#define CP_WAIT1() asm volatile("cp.async.wait_group 1;" ::: "memory")
#define CP_WAIT2() asm volatile("cp.async.wait_group 2;" ::: "memory")

#define LDSM_X4(r0, r1, r2, r3, a) \
  asm volatile("ldmatrix.sync.aligned.m8n8.x4.shared.b16 {%0,%1,%2,%3}, [%4];" \
               : "=r"(r0), "=r"(r1), "=r"(r2), "=r"(r3) : "r"(a))
#define LDSM_X4_T(r0, r1, r2, r3, a) \
  asm volatile("ldmatrix.sync.aligned.m8n8.x4.trans.shared.b16 {%0,%1,%2,%3}, [%4];" \
               : "=r"(r0), "=r"(r1), "=r"(r2), "=r"(r3) : "r"(a))

#define MMA16816(d, a0, a1, a2, a3, b0, b1) \
  asm volatile("mma.sync.aligned.m16n8k16.row.col.f32.f16.f16.f32 " \
               "{%0,%1,%2,%3}, {%4,%5,%6,%7}, {%8,%9}, {%0,%1,%2,%3};" \
               : "+f"((d)[0]), "+f"((d)[1]), "+f"((d)[2]), "+f"((d)[3]) \
               : "r"(a0), "r"(a1), "r"(a2), "r"(a3), "r"(b0), "r"(b1))

__device__ __forceinline__ float gelu_f(float v) {
  return 0.5f * v * (1.f + erff(v * 0.70710678118654752f));
}

// ========== RoPE LUT (identical math to prior in-epilogue computation) ====
__global__ __launch_bounds__(256) void rope_lut_kernel(float2* __restrict__ lut) {
  int idx = blockIdx.x * 256 + threadIdx.x;   // 2048*32 entries
  int n = idx >> 5, i = idx & 31;
  float inv = 1.0f / powf(10000.0f, (float)(2 * i) / 64.0f);
  float c, s;
  sincosf((float)n * inv, &s, &c);
  lut[idx] = make_float2(c, s);
}

// ========== weight convert + transpose (+optional row-scale fold) ==========
__global__ __launch_bounds__(256) void wconv_kernel(
    const float* __restrict__ W, const float* __restrict__ scale,
    __half* __restrict__ th, int K, int N) {
  __shared__ float t[64][33];
  int n0 = blockIdx.x * 32, k0 = blockIdx.y * 64;
  int tn = threadIdx.x & 31, tk = threadIdx.x >> 5;
#pragma unroll
  for (int i = 0; i < 8; i++)
    t[tk + i * 8][tn] = W[(size_t)(k0 + tk + i * 8) * N + n0 + tn];
  __syncthreads();
  int wn = threadIdx.x >> 3, wk = (threadIdx.x & 7) * 8;
  __half tmp[8];
#pragma unroll
  for (int i = 0; i < 8; i++) {
    float v = t[wk + i][wn];
    if (scale) v *= scale[k0 + wk + i];
    tmp[i] = __float2half_rn(v);
  }
  *(uint4*)(th + (size_t)(n0 + wn) * K + k0 + wk) = *(uint4*)tmp;
}

// ========== u/t partials: chunked column sums (deterministic) ==========
__global__ __launch_bounds__(256) void ut_part_kernel(
    const float* __restrict__ W, const float* __restrict__ g,
    const float* __restrict__ b, int N,
    float* __restrict__ pu, float* __restrict__ pt) {
  int n = blockIdx.x * 256 + threadIdx.x;
  int k0 = blockIdx.y * 128;
  float su = 0.f, st = 0.f;
  for (int c = 0; c < 128; c++) {
    float w = W[(size_t)(k0 + c) * N + n];
    su += g[k0 + c] * w;
    st += b[k0 + c] * w;
  }
  pu[(size_t)blockIdx.y * N + n] = su;
  pt[(size_t)blockIdx.y * N + n] = st;
}

__global__ __launch_bounds__(256) void ut_red_kernel(
    const float* __restrict__ pu, const float* __restrict__ pt, int nch,
    int N, float* __restrict__ u, float* __restrict__ t) {
  int n = blockIdx.x * 256 + threadIdx.x;
  float su = 0.f, st = 0.f;
  for (int i = 0; i < nch; i++) {
    su += pu[(size_t)i * N + n];
    st += pt[(size_t)i * N + n];
  }
  u[n] = su;
  t[n] = st;
}

// ================= LayerNorm (fp32 in, 1024) -> fp16 =================
__global__ __launch_bounds__(256) void ln_h_kernel(
    const float* __restrict__ in, const float* __restrict__ gw,
    const float* __restrict__ bw, __half* __restrict__ oh) {
  const int cols = 1024;
  int row = blockIdx.x;
  const float* rp = in + (size_t)row * cols;
  int c = threadIdx.x * 4;
  float4 v = *(const float4*)(rp + c);
  float s = v.x + v.y + v.z + v.w;
  float sq = v.x * v.x + v.y * v.y + v.z * v.z + v.w * v.w;
  __shared__ float red0[8], red1[8];
#pragma unroll
  for (int o = 16; o; o >>= 1) {
    s += __shfl_xor_sync(0xffffffff, s, o);
    sq += __shfl_xor_sync(0xffffffff, sq, o);
  }
  int warp = threadIdx.x >> 5, lane = threadIdx.x & 31;
  if (lane == 0) { red0[warp] = s; red1[warp] = sq; }
  __syncthreads();
  __shared__ float s_mu, s_ri;
  if (threadIdx.x == 0) {
    float ts = 0.f, tq = 0.f;
#pragma unroll
    for (int i = 0; i < 8; i++) { ts += red0[i]; tq += red1[i]; }
    float mu = ts / (float)cols;
    float var = tq / (float)cols - mu * mu;
    s_mu = mu;
    s_ri = rsqrtf(var + 1e-5f);
  }
  __syncthreads();
  float mu = s_mu, ri = s_ri;
  float4 g4 = *(const float4*)(gw + c);
  float4 b4 = *(const float4*)(bw + c);
  __half2 h01, h23;
  h01.x = __float2half_rn((v.x - mu) * ri * g4.x + b4.x);
  h01.y = __float2half_rn((v.y - mu) * ri * g4.y + b4.y);
  h23.x = __float2half_rn((v.z - mu) * ri * g4.z + b4.z);
  h23.y = __float2half_rn((v.w - mu) * ri * g4.w + b4.w);
  size_t o = (size_t)row * cols + c;
  *(__half2*)(oh + o) = h01;
  *(__half2*)(oh + o + 2) = h23;
}

// ================= mma.sync fp16 GEMM (BK=64, 3-stage) =================
#define GPITCH 144
#define TILE_H (128 * GPITCH)
#define STAGE_H (2 * TILE_H)
#define GEMM_SMEM (3 * STAGE_H)
#define GEMM_SMEM_X (GEMM_SMEM + 1024)
#define QSCALE 0.1803368801111244f

template <int EPI>
__global__ __launch_bounds__(256, 2) void gemm_mma(
    const __half* __restrict__ Ah, const __half* __restrict__ Bh,
    const float* __restrict__ bias, const float* __restrict__ res,
    const __half* __restrict__ resh,
    float* __restrict__ C, int K, int N,
    __half* hout, __half* k_, __half* v_,
    const float* __restrict__ pin_s, const float* __restrict__ pin_q,
    int nbin, float invNin,
    const float* __restrict__ uv, const float* __restrict__ tv,
    float* __restrict__ psum, float* __restrict__ psq, int nbp,
    const float2* __restrict__ rope) {
  extern __shared__ char smem[];
  uint32_t sb = smem_u32(smem);
  int tid = threadIdx.x, wid = tid >> 5, lane = tid & 31;
  int m0 = blockIdx.y * 128, n0 = blockIdx.x * 128;
  int wm = wid & 1, wn = wid >> 1;
  int lrow = lane & 15, lc8 = (lane >> 4) * 8;
  float* smu = (float*)(smem + GEMM_SMEM);
  float* sri = smu + 128;

  float acc[4][4][4];
#pragma unroll
  for (int i = 0; i < 4; i++)
#pragma unroll
    for (int j = 0; j < 4; j++)
#pragma unroll
      for (int t = 0; t < 4; t++) acc[i][j][t] = 0.f;

  int NCH = K >> 6;

#define GEMM_LOADS(stgbase, ktv)                                             \
  {                                                                          \
    uint32_t stg = (stgbase);                                                \
    int kt = (ktv);                                                          \
    _Pragma("unroll") for (int i = 0; i < 4; i++) {                          \
      int c = tid + i * 256;                                                 \
      int r = c >> 3, q = c & 7;                                             \
      uint32_t so = (uint32_t)(r * GPITCH + q * 16);                         \
      CP_ASYNC16(stg + so, Ah + (size_t)(m0 + r) * K + kt + q * 8);          \
      CP_ASYNC16(stg + TILE_H + so, Bh + (size_t)(n0 + r) * K + kt + q * 8); \
    }                                                                        \
    CP_COMMIT();                                                             \
  }

  GEMM_LOADS(sb, 0);
  GEMM_LOADS(sb + STAGE_H, 64);

  if ((EPI == 6 || EPI == 7) && tid < 128) {
    float s = 0.f, q = 0.f;
    for (int i = 0; i < nbin; i++) {
      s += pin_s[(size_t)(m0 + tid) * nbin + i];
      q += pin_q[(size_t)(m0 + tid) * nbin + i];
    }
    float m = s * invNin;
    float var = q * invNin - m * m;
    smu[tid] = m;
    sri[tid] = rsqrtf(var + 1e-5f);
  }

  for (int kc = 0; kc < NCH; kc++) {
    if (kc + 1 < NCH) { CP_WAIT1(); } else { CP_WAIT0(); }
    __syncthreads();
    if (kc + 2 < NCH) GEMM_LOADS(sb + ((kc + 2) % 3) * STAGE_H, (kc + 2) * 64);

    uint32_t stA = sb + (kc % 3) * STAGE_H;
    uint32_t stB = stA + TILE_H;

#pragma unroll
    for (int ks = 0; ks < 64; ks += 16) {
      uint32_t bhf[8];
      uint32_t boff0 = (uint32_t)((wn * 32 + lrow) * GPITCH + (ks + lc8) * 2);
      uint32_t boff1 = (uint32_t)((wn * 32 + 16 + lrow) * GPITCH + (ks + lc8) * 2);
      LDSM_X4(bhf[0], bhf[1], bhf[2], bhf[3], stB + boff0);
      LDSM_X4(bhf[4], bhf[5], bhf[6], bhf[7], stB + boff1);
#pragma unroll
      for (int mb = 0; mb < 4; mb++) {
        uint32_t ah[4];
        uint32_t aoff = (uint32_t)((wm * 64 + mb * 16 + lrow) * GPITCH + (ks + lc8) * 2);
        LDSM_X4(ah[0], ah[1], ah[2], ah[3], stA + aoff);
#pragma unroll
        for (int nb = 0; nb < 4; nb++) {
          int pi = (nb >> 1) * 4, od = nb & 1;
          MMA16816(acc[mb][nb], ah[0], ah[1], ah[2], ah[3],
                   bhf[pi + od], bhf[pi + 2 + od]);
        }
      }
    }
  }

  int erow = lane >> 2, ecol = (lane & 3) * 2;
  float rs[4][2], rq[4][2];
  if (EPI == 4 || EPI == 6) {
#pragma unroll
    for (int i = 0; i < 4; i++) {
      rs[i][0] = rs[i][1] = 0.f;
      rq[i][0] = rq[i][1] = 0.f;
    }
  }

#pragma unroll
  for (int mb = 0; mb < 4; mb++) {
    int gr = m0 + wm * 64 + mb * 16 + erow;
    int lr0 = wm * 64 + mb * 16 + erow;
    float mur0, rir0, mur1, rir1;
    if (EPI == 6 || EPI == 7) {
      mur0 = smu[lr0]; rir0 = sri[lr0];
      mur1 = smu[lr0 + 8]; rir1 = sri[lr0 + 8];
    }
#pragma unroll
    for (int nb = 0; nb < 4; nb++) {
      float* d = acc[mb][nb];
      int gc = n0 + wn * 32 + nb * 8 + ecol;
      float2 b2 = *(const float2*)(bias + gc);
      float v0, v1, v2, v3;
      if (EPI == 6 || EPI == 7) {
        float2 u2 = *(const float2*)(uv + gc);
        float2 t2 = *(const float2*)(tv + gc);
        v0 = rir0 * (d[0] - mur0 * u2.x) + t2.x + b2.x;
        v1 = rir0 * (d[1] - mur0 * u2.y) + t2.y + b2.y;
        v2 = rir1 * (d[2] - mur1 * u2.x) + t2.x + b2.x;
        v3 = rir1 * (d[3] - mur1 * u2.y) + t2.y + b2.y;
      } else {
        v0 = d[0] + b2.x; v1 = d[1] + b2.y;
        v2 = d[2] + b2.x; v3 = d[3] + b2.y;
      }
      if (EPI == 3) {
        int region = gc >> 10;
        int hh = (gc & 1023) >> 6;
        int dd = gc & 63;
        int b = gr >> 11;
        int n = gr & 2047;
        if (region < 2) {
          float2 cs0 = rope[n * 32 + (dd >> 1)];
          float2 cs1 = rope[(n + 8) * 32 + (dd >> 1)];
          float r0 = v0 * cs0.x - v1 * cs0.y, r1 = v1 * cs0.x + v0 * cs0.y;
          float r2 = v2 * cs1.x - v3 * cs1.y, r3 = v3 * cs1.x + v2 * cs1.y;
          v0 = r0; v1 = r1; v2 = r2; v3 = r3;
          if (region == 0) { v0 *= QSCALE; v1 *= QSCALE; v2 *= QSCALE; v3 *= QSCALE; }
        }
        __half* dst = (region == 0) ? hout : (region == 1) ? k_ : v_;
        size_t o0 = ((size_t)((b * 16 + hh) * 2048 + n)) * 64 + dd;
        size_t o1 = o0 + 8 * 64;
        *(__half2*)(dst + o0) = __floats2half2_rn(v0, v1);
        *(__half2*)(dst + o1) = __floats2half2_rn(v2, v3);
      } else if (EPI == 4) {
        float2 r0 = *(const float2*)(res + (size_t)gr * N + gc);
        float2 r1 = *(const float2*)(res + (size_t)(gr + 8) * N + gc);
        v0 += r0.x; v1 += r0.y; v2 += r1.x; v3 += r1.y;
        rs[mb][0] += v0 + v1; rq[mb][0] += v0 * v0 + v1 * v1;
        rs[mb][1] += v2 + v3; rq[mb][1] += v2 * v2 + v3 * v3;
        *(__half2*)(hout + (size_t)gr * N + gc) = __floats2half2_rn(v0, v1);
        *(__half2*)(hout + (size_t)(gr + 8) * N + gc) = __floats2half2_rn(v2, v3);
      } else if (EPI == 6) {
        v0 = gelu_f(v0); v1 = gelu_f(v1);
        v2 = gelu_f(v2); v3 = gelu_f(v3);
        rs[mb][0] += v0 + v1; rq[mb][0] += v0 * v0 + v1 * v1;
        rs[mb][1] += v2 + v3; rq[mb][1] += v2 * v2 + v3 * v3;
        *(__half2*)(hout + (size_t)gr * N + gc) = __floats2half2_rn(v0, v1);
        *(__half2*)(hout + (size_t)(gr + 8) * N + gc) = __floats2half2_rn(v2, v3);
      } else if (EPI == 7) {
        __half2 r0 = *(const __half2*)(resh + (size_t)gr * N + gc);
        __half2 r1 = *(const __half2*)(resh + (size_t)(gr + 8) * N + gc);
        float2 f0 = __half22float2(r0), f1 = __half22float2(r1);
        v0 += f0.x; v1 += f0.y; v2 += f1.x; v3 += f1.y;
        float2 o0 = {v0, v1}, o1 = {v2, v3};
        *(float2*)(C + (size_t)gr * N + gc) = o0;
        *(float2*)(C + (size_t)(gr + 8) * N + gc) = o1;
      }
    }
  }

  if (EPI == 4 || EPI == 6) {
    __syncthreads();
    float2* part = (float2*)smem;
#pragma unroll
    for (int mb = 0; mb < 4; mb++) {
#pragma unroll
      for (int h = 0; h < 2; h++) {
        float s = rs[mb][h], q = rq[mb][h];
        s += __shfl_xor_sync(0xffffffff, s, 1);
        s += __shfl_xor_sync(0xffffffff, s, 2);
        q += __shfl_xor_sync(0xffffffff, q, 1);
        q += __shfl_xor_sync(0xffffffff, q, 2);
        if ((lane & 3) == 0) {
          int r = wm * 64 + mb * 16 + erow + h * 8;
          float2 sq2 = {s, q};
          part[r * 4 + wn] = sq2;
        }
      }
    }
    __syncthreads();
    if (tid < 128) {
      float2 a = part[tid * 4 + 0], b = part[tid * 4 + 1];
      float2 c = part[tid * 4 + 2], dd = part[tid * 4 + 3];
      psum[(size_t)(m0 + tid) * nbp + blockIdx.x] = a.x + b.x + c.x + dd.x;
      psq[(size_t)(m0 + tid) * nbp + blockIdx.x] = a.y + b.y + c.y + dd.y;
    }
  }
}

// ================= FA2 flash attention (4-stage KV ring) =================
#define APB 144
#define A_oQ 0
#define A_oKV 18432
#define ATTN_SMEM (18432 + 4 * 18432)   // 92160

__global__ __launch_bounds__(256, 2) void attn_mma(
    const __half* __restrict__ qg, const __half* __restrict__ kg_,
    const __half* __restrict__ vg, __half* __restrict__ og) {
  extern __shared__ char sm[];
  uint32_t sb = smem_u32(sm);

  int tid = threadIdx.x, wid = tid >> 5, lane = tid & 31;
  int lrow = lane & 15, lc8 = (lane >> 4) * 8;
  int erow = lane >> 2, ecol = (lane & 3) * 2;
  int bh = blockIdx.y, qt = blockIdx.x;
  size_t base = (size_t)bh * (2048 * 64);

  {
    const __half* gq = qg + base + (size_t)(qt * 128) * 64;
#pragma unroll
    for (int i = 0; i < 4; i++) {
      int f = tid + i * 256;
      int r = f >> 3, c8 = f & 7;
      CP_ASYNC16(sb + A_oQ + (uint32_t)(r * APB + c8 * 16), gq + r * 64 + c8 * 8);
    }
    CP_COMMIT();
  }

#define ATTN_KV_LOADS(stg, ktv)                                              \
  {                                                                          \
    int kt_ = (ktv);                                                         \
    uint32_t d0 = sb + A_oKV + (stg) * 18432;                                \
    _Pragma("unroll") for (int i = 0; i < 2; i++) {                          \
      int f = tid + i * 256;                                                 \
      int r = f >> 3, c8 = f & 7;                                            \
      uint32_t so = (uint32_t)(r * APB + c8 * 16);                           \
      size_t go = base + (size_t)(kt_ * 64 + r) * 64 + c8 * 8;               \
      CP_ASYNC16(d0 + so, kg_ + go);                                         \
      CP_ASYNC16(d0 + 9216 + so, vg + go);                                   \
    }                                                                        \
    CP_COMMIT();                                                             \
  }

  ATTN_KV_LOADS(0, 0);
  ATTN_KV_LOADS(1, 1);
  ATTN_KV_LOADS(2, 2);

  float oacc[8][4];
#pragma unroll
  for (int j = 0; j < 8; j++)
#pragma unroll
    for (int t = 0; t < 4; t++) oacc[j][t] = 0.f;
  float m_lo = -INFINITY, m_hi = -INFINITY, l_lo = 0.f, l_hi = 0.f;

  uint32_t qbase = sb + A_oQ + (uint32_t)((wid * 16 + lrow) * APB + lc8 * 2);
  uint32_t aq[4][4];

  for (int kt = 0; kt < 32; kt++) {
    if (kt <= 29) { CP_WAIT2(); } else if (kt == 30) { CP_WAIT1(); } else { CP_WAIT0(); }
    __syncthreads();
    if (kt + 3 < 32) ATTN_KV_LOADS((kt + 3) & 3, kt + 3);
    if (kt == 0) {
#pragma unroll
      for (int ks = 0; ks < 4; ks++)
        LDSM_X4(aq[ks][0], aq[ks][1], aq[ks][2], aq[ks][3], qbase + ks * 32);
    }

    uint32_t sK = sb + A_oKV + (kt & 3) * 18432;
    uint32_t sV = sK + 9216;

    float sacc[8][4];
#pragma unroll
    for (int j = 0; j < 8; j++)
#pragma unroll
      for (int t = 0; t < 4; t++) sacc[j][t] = 0.f;
#pragma unroll
    for (int ks = 0; ks < 4; ks++) {
#pragma unroll
      for (int g = 0; g < 4; g++) {
        uint32_t kb[4];
        uint32_t koff = (uint32_t)((g * 16 + lrow) * APB + (ks * 16 + lc8) * 2);
        LDSM_X4(kb[0], kb[1], kb[2], kb[3], sK + koff);
        MMA16816(sacc[g * 2 + 0], aq[ks][0], aq[ks][1], aq[ks][2], aq[ks][3],
                 kb[0], kb[2]);
        MMA16816(sacc[g * 2 + 1], aq[ks][0], aq[ks][1], aq[ks][2], aq[ks][3],
                 kb[1], kb[3]);
      }
    }

    float mx0 = -INFINITY, mx1 = -INFINITY;
#pragma unroll
    for (int j = 0; j < 8; j++) {
      mx0 = fmaxf(mx0, fmaxf(sacc[j][0], sacc[j][1]));
      mx1 = fmaxf(mx1, fmaxf(sacc[j][2], sacc[j][3]));
    }
    mx0 = fmaxf(mx0, __shfl_xor_sync(0xffffffff, mx0, 1));
    mx0 = fmaxf(mx0, __shfl_xor_sync(0xffffffff, mx0, 2));
    mx1 = fmaxf(mx1, __shfl_xor_sync(0xffffffff, mx1, 1));
    mx1 = fmaxf(mx1, __shfl_xor_sync(0xffffffff, mx1, 2));
    float nm0 = fmaxf(m_lo, mx0), nm1 = fmaxf(m_hi, mx1);
    float cf0 = exp2f(m_lo - nm0), cf1 = exp2f(m_hi - nm1);
    m_lo = nm0; m_hi = nm1;

    uint32_t pa[4][4];
    float s0 = 0.f, s1 = 0.f;
#pragma unroll
    for (int g = 0; g < 4; g++) {
#pragma unroll
      for (int hb = 0; hb < 2; hb++) {
        int j = g * 2 + hb;
        float p00 = exp2f(sacc[j][0] - nm0);
        float p01 = exp2f(sacc[j][1] - nm0);
        float p10 = exp2f(sacc[j][2] - nm1);
        float p11 = exp2f(sacc[j][3] - nm1);
        s0 += p00 + p01;
        s1 += p10 + p11;
        __half2 plo = __floats2half2_rn(p00, p01);
        __half2 phi = __floats2half2_rn(p10, p11);
        pa[g][hb * 2 + 0] = *(uint32_t*)&plo;
        pa[g][hb * 2 + 1] = *(uint32_t*)&phi;
      }
    }
    s0 += __shfl_xor_sync(0xffffffff, s0, 1);
    s0 += __shfl_xor_sync(0xffffffff, s0, 2);
    s1 += __shfl_xor_sync(0xffffffff, s1, 1);
    s1 += __shfl_xor_sync(0xffffffff, s1, 2);
    l_lo = l_lo * cf0 + s0;
    l_hi = l_hi * cf1 + s1;

#pragma unroll
    for (int j = 0; j < 8; j++) {
      oacc[j][0] *= cf0; oacc[j][1] *= cf0;
      oacc[j][2] *= cf1; oacc[j][3] *= cf1;
    }
#pragma unroll
    for (int g = 0; g < 4; g++) {
#pragma unroll
      for (int db = 0; db < 4; db++) {
        uint32_t vb[4];
        uint32_t voff = (uint32_t)((g * 16 + lrow) * APB + (db * 16 + lc8) * 2);
        LDSM_X4_T(vb[0], vb[1], vb[2], vb[3], sV + voff);
        MMA16816(oacc[db * 2 + 0], pa[g][0], pa[g][1], pa[g][2], pa[g][3],
                 vb[0], vb[1]);
        MMA16816(oacc[db * 2 + 1], pa[g][0], pa[g][1], pa[g][2], pa[g][3],
                 vb[2], vb[3]);
      }
    }
  }

  int b = bh >> 4, h = bh & 15;
  float il0 = 1.f / l_lo, il1 = 1.f / l_hi;
  int qrow = qt * 128 + wid * 16 + erow;
  size_t rbase0 = ((size_t)(b * 2048 + qrow)) * 1024 + h * 64;
  size_t rbase1 = rbase0 + 8 * 1024;
#pragma unroll
  for (int db = 0; db < 4; db++) {
#pragma unroll
    for (int nb = 0; nb < 2; nb++) {
      int j = db * 2 + nb;
      int d = db * 16 + nb * 8 + ecol;
      *(__half2*)(og + rbase0 + d) = __floats2half2_rn(oacc[j][0] * il0,
                                                       oacc[j][1] * il0);
      *(__half2*)(og + rbase1 + d) = __floats2half2_rn(oacc[j][2] * il1,
                                                       oacc[j][3] * il1);
    }
  }
}

// ================= launch =================
extern "C" void kernel_launch(void* const* d_in, const int* in_sizes, int n_in,
                              void* d_out, int out_size) {
  const float* x = (const float*)d_in[0];
  const float* ln1_g = (const float*)d_in[1];
  const float* ln1_b = (const float*)d_in[2];
  const float* qkv_w = (const float*)d_in[3];
  const float* qkv_b = (const float*)d_in[4];
  const float* proj_w = (const float*)d_in[5];
  const float* proj_b = (const float*)d_in[6];
  const float* ln2_g = (const float*)d_in[7];
  const float* ln2_b = (const float*)d_in[8];
  const float* fc1_w = (const float*)d_in[9];
  const float* fc1_b = (const float*)d_in[10];
  const float* ffln_g = (const float*)d_in[11];
  const float* ffln_b = (const float*)d_in[12];
  const float* fc2_w = (const float*)d_in[13];
  const float* fc2_b = (const float*)d_in[14];
  float* out = (float*)d_out;

  __half *x1h, *h1h, *ah, *att, *q, *k, *v;
  __half *wq, *wp, *w1, *w2;
  float *ps1, *pq1, *ps2, *pq2, *u1, *t1, *u2, *t2, *pu, *pt;
  float2* rope;
  cudaGetSymbolAddress((void**)&x1h, g_x1h);
  cudaGetSymbolAddress((void**)&h1h, g_h1h);
  cudaGetSymbolAddress((void**)&ah, g_ah);
  cudaGetSymbolAddress((void**)&att, g_att);
  cudaGetSymbolAddress((void**)&q, g_q2);
  cudaGetSymbolAddress((void**)&k, g_k2);
  cudaGetSymbolAddress((void**)&v, g_v2);
  cudaGetSymbolAddress((void**)&wq, g_wq);
  cudaGetSymbolAddress((void**)&wp, g_wp);
  cudaGetSymbolAddress((void**)&w1, g_w1);
  cudaGetSymbolAddress((void**)&w2, g_w2);
  cudaGetSymbolAddress((void**)&ps1, g_ps1);
  cudaGetSymbolAddress((void**)&pq1, g_pq1);
  cudaGetSymbolAddress((void**)&ps2, g_ps2);
  cudaGetSymbolAddress((void**)&pq2, g_pq2);
  cudaGetSymbolAddress((void**)&u1, g_u1);
  cudaGetSymbolAddress((void**)&t1, g_t1);
  cudaGetSymbolAddress((void**)&u2, g_u2);
  cudaGetSymbolAddress((void**)&t2, g_t2);
  cudaGetSymbolAddress((void**)&pu, g_pu);
  cudaGetSymbolAddress((void**)&pt, g_pt);
  cudaGetSymbolAddress((void**)&rope, g_rope);

  cudaFuncSetAttribute(gemm_mma<3>, cudaFuncAttributeMaxDynamicSharedMemorySize, GEMM_SMEM_X);
  cudaFuncSetAttribute(gemm_mma<4>, cudaFuncAttributeMaxDynamicSharedMemorySize, GEMM_SMEM_X);
  cudaFuncSetAttribute(gemm_mma<6>, cudaFuncAttributeMaxDynamicSharedMemorySize, GEMM_SMEM_X);
  cudaFuncSetAttribute(gemm_mma<7>, cudaFuncAttributeMaxDynamicSharedMemorySize, GEMM_SMEM_X);
  cudaFuncSetAttribute(attn_mma, cudaFuncAttributeMaxDynamicSharedMemorySize, ATTN_SMEM);

  // --- side stream: rope LUT + weight conversion + u/t vectors ---
  cudaStream_t s1;
  cudaStreamCreateWithFlags(&s1, cudaStreamNonBlocking);
  cudaEvent_t evRoot, evQ, evP, evW;
  cudaEventCreateWithFlags(&evRoot, cudaEventDisableTiming);
  cudaEventCreateWithFlags(&evQ, cudaEventDisableTiming);
  cudaEventCreateWithFlags(&evP, cudaEventDisableTiming);
  cudaEventCreateWithFlags(&evW, cudaEventDisableTiming);

  cudaEventRecord(evRoot, 0);
  cudaStreamWaitEvent(s1, evRoot, 0);

  rope_lut_kernel<<<(NNq * 32) / 256, 256, 0, s1>>>(rope);
  wconv_kernel<<<dim3(3072 / 32, 1024 / 64), 256, 0, s1>>>(qkv_w, nullptr, wq, 1024, 3072);
  cudaEventRecord(evQ, s1);
  wconv_kernel<<<dim3(1024 / 32, 1024 / 64), 256, 0, s1>>>(proj_w, nullptr, wp, 1024, 1024);
  cudaEventRecord(evP, s1);
  wconv_kernel<<<dim3(4096 / 32, 1024 / 64), 256, 0, s1>>>(fc1_w, ln2_g, w1, 1024, 4096);
  wconv_kernel<<<dim3(1024 / 32, 4096 / 64), 256, 0, s1>>>(fc2_w, ffln_g, w2, 4096, 1024);
  ut_part_kernel<<<dim3(4096 / 256, 1024 / 128), 256, 0, s1>>>(fc1_w, ln2_g, ln2_b, 4096, pu, pt);
  ut_red_kernel<<<4096 / 256, 256, 0, s1>>>(pu, pt, 8, 4096, u1, t1);
  ut_part_kernel<<<dim3(1024 / 256, 4096 / 128), 256, 0, s1>>>(fc2_w, ffln_g, ffln_b, 1024, pu, pt);
  ut_red_kernel<<<1024 / 256, 256, 0, s1>>>(pu, pt, 32, 1024, u2, t2);
  cudaEventRecord(evW, s1);

  // main branch
  // 1) LN1 -> fp16
  ln_h_kernel<<<ROWS, 256>>>(x, ln1_g, ln1_b, ah);
  // 2) QKV GEMM (needs wq + rope LUT)
  cudaStreamWaitEvent(0, evQ, 0);
  gemm_mma<3><<<dim3(3072 / 128, ROWS / 128), 256, GEMM_SMEM_X>>>(
      ah, wq, qkv_b, nullptr, nullptr, nullptr, 1024, 3072, q, k, v,
      nullptr, nullptr, 0, 0.f, nullptr, nullptr, nullptr, nullptr, 0, rope);
  // 3) attention
  attn_mma<<<dim3(NNq / 128, BB * HHn), 256, ATTN_SMEM>>>(q, k, v, att);
  // 4) proj + residual(x) -> x1h + stats partials
  cudaStreamWaitEvent(0, evP, 0);
  gemm_mma<4><<<dim3(1024 / 128, ROWS / 128), 256, GEMM_SMEM_X>>>(
      att, wp, proj_b, x, nullptr, nullptr, 1024, 1024, x1h, nullptr, nullptr,
      nullptr, nullptr, 0, 0.f, nullptr, nullptr, ps1, pq1, 8, nullptr);
  // 5) fc1 (LN2 folded, in-prologue stats) + GELU -> h1h + partials
  cudaStreamWaitEvent(0, evW, 0);
  gemm_mma<6><<<dim3(4096 / 128, ROWS / 128), 256, GEMM_SMEM_X>>>(
      x1h, w1, fc1_b, nullptr, nullptr, nullptr, 1024, 4096, h1h, nullptr, nullptr,
      ps1, pq1, 8, 1.0f / 1024.0f, u1, t1, ps2, pq2, 32, nullptr);
  // 6) fc2 (ffn-LN folded, in-prologue stats) + residual(x1h) -> out fp32
  gemm_mma<7><<<dim3(1024 / 128, ROWS / 128), 256, GEMM_SMEM_X>>>(
      h1h, w2, fc2_b, nullptr, x1h, out, 4096, 1024, nullptr, nullptr, nullptr,
      ps2, pq2, 32, 1.0f / 4096.0f, u2, t2, nullptr, nullptr, 0, nullptr);
}